// round 1
// baseline (speedup 1.0000x reference)
#include <cuda_runtime.h>
#include <cstddef>

#define NVV   40962
#define NVP   10242
#define BB    8
#define CC    64
#define KK    7
#define VBLKS 1281              // ceil(40962/32)
#define GN_N  (2*NVV)           // elements per groupnorm group (2 channels * NV)

// Scratch (device globals — no allocations allowed)
__device__ float d_Y[(size_t)BB * NVP * 256];   // [b][v'][s*64+o], ~84 MB
__device__ float d_psum[256 * VBLKS];           // per (b*32+g, vblk) partial sums
__device__ float d_psq [256 * VBLKS];
__device__ float d_mean[256];
__device__ float d_rstd[256];

// ---------------------------------------------------------------------------
// Stage 1: Y[b, v', s*64+o] = sum_i coeffs[o,i,s] * x[b,i,v']
// GEMM (256 x 64) @ (64 x 10242) per batch. fp32, register-tiled 8x8.
// ---------------------------------------------------------------------------
__global__ void __launch_bounds__(256) k_stage1(const float* __restrict__ x,
                                                const float* __restrict__ coeffs)
{
    extern __shared__ float sm[];
    float* cst = sm;             // [i][so] : 64*256 = 64 KB
    float* xs  = sm + 64 * 256;  // [i][vl] : 64*64  = 16 KB

    const int b     = blockIdx.y;
    const int vbase = blockIdx.x * 64;
    const int tid   = threadIdx.x;

    // Load coeffs transposed: cst[i*256 + (s*64+o)] = coeffs[(o*64+i)*4 + s]
    for (int t = tid; t < 64 * 256; t += 256) {
        int i  = t >> 8;
        int so = t & 255;
        int o  = so & 63;
        int s  = so >> 6;
        cst[t] = coeffs[(o * 64 + i) * 4 + s];
    }
    // Load x tile [64 ch][64 v], zero-padded past NVP
    for (int t = tid; t < 64 * 64; t += 256) {
        int i  = t >> 6;
        int vl = t & 63;
        int v  = vbase + vl;
        xs[t]  = (v < NVP) ? x[(b * 64 + i) * NVP + v] : 0.f;
    }
    __syncthreads();

    const int so0 = (tid & 31) * 8;   // 32 lanes cover 256 outputs
    const int v0  = (tid >> 5) * 8;   // 8 warps cover 64 vertices

    float acc[8][8];
#pragma unroll
    for (int a = 0; a < 8; a++)
#pragma unroll
        for (int c = 0; c < 8; c++) acc[a][c] = 0.f;

#pragma unroll 4
    for (int i = 0; i < 64; i++) {
        float4 c0 = *(const float4*)&cst[i * 256 + so0];
        float4 c1 = *(const float4*)&cst[i * 256 + so0 + 4];
        float4 x0 = *(const float4*)&xs[i * 64 + v0];
        float4 x1 = *(const float4*)&xs[i * 64 + v0 + 4];
        float cv[8] = {c0.x, c0.y, c0.z, c0.w, c1.x, c1.y, c1.z, c1.w};
        float xv[8] = {x0.x, x0.y, x0.z, x0.w, x1.x, x1.y, x1.z, x1.w};
#pragma unroll
        for (int a = 0; a < 8; a++)
#pragma unroll
            for (int c = 0; c < 8; c++) acc[a][c] = fmaf(cv[a], xv[c], acc[a][c]);
    }

    // Store: per vertex, 8 contiguous "so" floats (32B-aligned)
#pragma unroll
    for (int c = 0; c < 8; c++) {
        int v = vbase + v0 + c;
        if (v < NVP) {
            float* dst = d_Y + (((size_t)b * NVP + v) * 256 + so0);
            float4 w0 = make_float4(acc[0][c], acc[1][c], acc[2][c], acc[3][c]);
            float4 w1 = make_float4(acc[4][c], acc[5][c], acc[6][c], acc[7][c]);
            *(float4*)dst       = w0;
            *(float4*)(dst + 4) = w1;
        }
    }
}

// ---------------------------------------------------------------------------
// Stage 2: gather-combine + pre-GN output + deterministic group partial sums.
// Block = (64 o-threads) x (4 v-lanes), 32 vertices per block.
// out_pre[b,o,v] = bias[o] + [v<NVP] y0[b,v,o]
//                + sum_k [idx<NVP] ( L*y1[idx] + EW*y2[idx] + NS*y3[idx] )[o]
// ---------------------------------------------------------------------------
__global__ void __launch_bounds__(256) k_stage2(const float* __restrict__ Lw,
                                                const float* __restrict__ Ew,
                                                const float* __restrict__ Nw,
                                                const int*   __restrict__ nbr,
                                                const float* __restrict__ bias,
                                                float* __restrict__ out)
{
    __shared__ int   s_idx[32 * KK];
    __shared__ float s_L[32 * KK], s_E[32 * KK], s_N[32 * KK];
    __shared__ float tile[64][33];          // [o][vl], +1 pad: conflict-free
    __shared__ float ss[4][64], sq[4][64];

    const int b     = blockIdx.y;
    const int vbase = blockIdx.x * 32;
    const int tx    = threadIdx.x;          // o
    const int ty    = threadIdx.y;          // v sub-lane
    const int tid   = ty * 64 + tx;

    if (tid < 32 * KK) {
        int gidx = vbase * KK + tid;
        if (gidx < NVV * KK) {
            s_idx[tid] = nbr[gidx];
            s_L[tid] = Lw[gidx]; s_E[tid] = Ew[gidx]; s_N[tid] = Nw[gidx];
        } else {
            s_idx[tid] = NVP; s_L[tid] = 0.f; s_E[tid] = 0.f; s_N[tid] = 0.f;
        }
    }
    __syncthreads();

    const float* Yb = d_Y + (size_t)b * NVP * 256;
    const float  bo = bias[tx];
    float S = 0.f, Q = 0.f;

#pragma unroll
    for (int iter = 0; iter < 8; iter++) {
        int vl = iter * 4 + ty;
        int v  = vbase + vl;
        float acc = 0.f;
        if (v < NVV) {
            acc = bo;
            if (v < NVP) acc += Yb[v * 256 + tx];
#pragma unroll
            for (int k = 0; k < KK; k++) {
                int j = s_idx[vl * KK + k];
                if (j < NVP) {                     // warp-uniform branch
                    const float* p = Yb + j * 256 + tx;
                    acc = fmaf(s_L[vl * KK + k], p[64],  acc);
                    acc = fmaf(s_E[vl * KK + k], p[128], acc);
                    acc = fmaf(s_N[vl * KK + k], p[192], acc);
                }
            }
            S += acc;
            Q = fmaf(acc, acc, Q);
        }
        tile[tx][vl] = acc;
    }
    ss[ty][tx] = S;
    sq[ty][tx] = Q;
    __syncthreads();

    // Transposed write-out: each thread writes 8 consecutive v of one o-row
    {
        int r   = tid >> 2;
        int seg = tid & 3;
        size_t rowbase = (size_t)(b * 64 + r) * NVV;
#pragma unroll
        for (int u = 0; u < 8; u++) {
            int vl = seg * 8 + u;
            int v  = vbase + vl;
            if (v < NVV) out[rowbase + v] = tile[r][vl];
        }
    }

    // Deterministic per-(b,group,vblk) partials: group g = channels {2g, 2g+1}
    if (tid < 32) {
        float Sg = 0.f, Qg = 0.f;
#pragma unroll
        for (int oo = 0; oo < 2; oo++)
#pragma unroll
            for (int yy = 0; yy < 4; yy++) {
                Sg += ss[yy][tid * 2 + oo];
                Qg += sq[yy][tid * 2 + oo];
            }
        d_psum[(b * 32 + tid) * VBLKS + blockIdx.x] = Sg;
        d_psq [(b * 32 + tid) * VBLKS + blockIdx.x] = Qg;
    }
}

// ---------------------------------------------------------------------------
// Stage 2.5: reduce partials -> mean / rstd per (b, group). Fixed-order.
// ---------------------------------------------------------------------------
__global__ void __launch_bounds__(256) k_reduce()
{
    __shared__ float sS[256], sQ[256];
    const int bg  = blockIdx.x;
    const int tid = threadIdx.x;
    float S = 0.f, Q = 0.f;
    for (int i = tid; i < VBLKS; i += 256) {
        S += d_psum[bg * VBLKS + i];
        Q += d_psq [bg * VBLKS + i];
    }
    sS[tid] = S; sQ[tid] = Q;
    __syncthreads();
    for (int st = 128; st > 0; st >>= 1) {
        if (tid < st) { sS[tid] += sS[tid + st]; sQ[tid] += sQ[tid + st]; }
        __syncthreads();
    }
    if (tid == 0) {
        float mean = sS[0] * (1.f / (float)GN_N);
        float var  = sQ[0] * (1.f / (float)GN_N) - mean * mean;
        d_mean[bg] = mean;
        d_rstd[bg] = rsqrtf(var + 1e-5f);
    }
}

// ---------------------------------------------------------------------------
// Stage 3: in-place normalize + affine + ReLU
// ---------------------------------------------------------------------------
__global__ void __launch_bounds__(256) k_stage3(float* __restrict__ out,
                                                const float* __restrict__ gamma,
                                                const float* __restrict__ beta)
{
    const int row = blockIdx.y;                 // b*64 + o
    const int o   = row & 63;
    const int bg  = (row >> 6) * 32 + (o >> 1);
    const int v   = blockIdx.x * 256 + threadIdx.x;
    if (v < NVV) {
        float a = d_rstd[bg] * gamma[o];
        float c = beta[o] - d_mean[bg] * a;
        size_t idx = (size_t)row * NVV + v;
        float val  = fmaf(out[idx], a, c);
        out[idx]   = fmaxf(val, 0.f);
    }
}

// ---------------------------------------------------------------------------
extern "C" void kernel_launch(void* const* d_in, const int* in_sizes, int n_in,
                              void* d_out, int out_size)
{
    const float* x      = (const float*)d_in[0];
    const float* L_val  = (const float*)d_in[1];
    const float* EW_val = (const float*)d_in[2];
    const float* NS_val = (const float*)d_in[3];
    const float* coeffs = (const float*)d_in[4];
    const float* bias   = (const float*)d_in[5];
    const float* gamma  = (const float*)d_in[6];
    const float* beta   = (const float*)d_in[7];
    const int*   nbr    = (const int*)  d_in[8];
    float*       out    = (float*)d_out;

    static bool configured = false;
    if (!configured) {
        cudaFuncSetAttribute(k_stage1, cudaFuncAttributeMaxDynamicSharedMemorySize,
                             (64 * 256 + 64 * 64) * (int)sizeof(float));
        configured = true;
    }

    // Stage 1: Y projection GEMM
    {
        dim3 grid((NVP + 63) / 64, BB);
        k_stage1<<<grid, 256, (64 * 256 + 64 * 64) * sizeof(float)>>>(x, coeffs);
    }
    // Stage 2: gather-combine + pre-GN out + partials
    {
        dim3 grid(VBLKS, BB);
        dim3 block(64, 4);
        k_stage2<<<grid, block>>>(L_val, EW_val, NS_val, nbr, bias, out);
    }
    // Stage 2.5: group statistics
    k_reduce<<<256, 256>>>();
    // Stage 3: normalize + ReLU (in place)
    {
        dim3 grid((NVV + 255) / 256, BB * CC);
        k_stage3<<<grid, 256>>>(out, gamma, beta);
    }
}

// round 3
// speedup vs baseline: 1.4403x; 1.4403x over previous
#include <cuda_runtime.h>
#include <cstddef>

#define NVV   40962
#define NVP   10242
#define BB    8
#define CC    64
#define KK    7
#define VBLKS 1281              // ceil(40962/32)
#define GN_N  (2*NVV)           // elements per groupnorm group (2 channels * NV)

#define TM 128
#define TN 128

// Scratch (device globals — no allocations allowed)
__device__ float d_Y[(size_t)BB * NVP * 256];   // [b][v'][s*64+o], ~84 MB
__device__ float d_psum[256 * VBLKS];           // per (b*32+g, vblk) partial sums
__device__ float d_psq [256 * VBLKS];
__device__ float d_mean[256];
__device__ float d_rstd[256];

#define FMA2(d, a, b, c) \
    asm("fma.rn.f32x2 %0, %1, %2, %3;" : "=l"(d) : "l"(a), "l"(b), "l"(c))

// ---------------------------------------------------------------------------
// Stage 1: Y[b, v', s*64+o] = sum_i coeffs[o,i,s] * x[b,i,v']
// GEMM (256 x 64) @ (64 x 10242) per batch. Packed f32x2 FMA, 128x128 tiles.
// ---------------------------------------------------------------------------
__global__ void __launch_bounds__(256) k_stage1(const float* __restrict__ x,
                                                const float* __restrict__ coeffs)
{
    extern __shared__ float sm[];
    float* As = sm;              // [i][vl] : 64*128
    float* Bs = sm + 64 * TM;    // [i][sol]: 64*128

    const int b      = blockIdx.z;
    const int vbase  = blockIdx.x * TM;
    const int sobase = blockIdx.y * TN;
    const int tid    = threadIdx.x;

    // Load B tile: Bs[i][sol] = coeffs[(o*64+i)*4 + s], so = sobase+sol
    for (int t = tid; t < 64 * TN; t += 256) {
        int i   = t >> 7;
        int sol = t & 127;
        int so  = sobase + sol;
        int o   = so & 63;
        int s   = so >> 6;
        Bs[t] = coeffs[(o * 64 + i) * 4 + s];
    }
    // Load A tile [64 ch][128 v], zero-padded past NVP
    for (int t = tid; t < 64 * TM; t += 256) {
        int i  = t >> 7;
        int vl = t & 127;
        int v  = vbase + vl;
        As[t]  = (v < NVP) ? x[(b * 64 + i) * NVP + v] : 0.f;
    }
    __syncthreads();

    const int so_sub = (tid & 15) * 8;   // 16 lanes cover 128 so
    const int v_sub  = (tid >> 4) * 8;   // 16 groups cover 128 v

    unsigned long long acc[8][4];        // [so][v-pair] packed f32x2
#pragma unroll
    for (int a = 0; a < 8; a++)
#pragma unroll
        for (int c = 0; c < 4; c++) acc[a][c] = 0ULL;

#pragma unroll 4
    for (int i = 0; i < 64; i++) {
        const ulonglong2* Ap = (const ulonglong2*)(As + i * TM + v_sub);
        ulonglong2 a01 = Ap[0];
        ulonglong2 a23 = Ap[1];
        unsigned long long av[4] = {a01.x, a01.y, a23.x, a23.y};
        float4 b0 = *(const float4*)(Bs + i * TN + so_sub);
        float4 b1 = *(const float4*)(Bs + i * TN + so_sub + 4);
        float bv[8] = {b0.x, b0.y, b0.z, b0.w, b1.x, b1.y, b1.z, b1.w};
#pragma unroll
        for (int a = 0; a < 8; a++) {
            unsigned bu = __float_as_uint(bv[a]);
            unsigned long long bb;
            asm("mov.b64 %0, {%1, %1};" : "=l"(bb) : "r"(bu));
#pragma unroll
            for (int c = 0; c < 4; c++)
                FMA2(acc[a][c], av[c], bb, acc[a][c]);
        }
    }

    // Store: per vertex, 8 contiguous "so" floats
#pragma unroll
    for (int c = 0; c < 4; c++) {
#pragma unroll
        for (int par = 0; par < 2; par++) {
            int v = vbase + v_sub + c * 2 + par;
            if (v < NVP) {
                float w[8];
#pragma unroll
                for (int a = 0; a < 8; a++) {
                    unsigned long long u = acc[a][c];
                    w[a] = __uint_as_float(par ? (unsigned)(u >> 32)
                                               : (unsigned)(u & 0xffffffffULL));
                }
                float* dst = d_Y + (((size_t)b * NVP + v) * 256 + sobase + so_sub);
                *(float4*)dst       = make_float4(w[0], w[1], w[2], w[3]);
                *(float4*)(dst + 4) = make_float4(w[4], w[5], w[6], w[7]);
            }
        }
    }
}

// ---------------------------------------------------------------------------
// Stage 2: gather-combine + pre-GN output + deterministic group partial sums.
// Neighbor list compacted per vertex (only idx<NVP survive, ~25%).
// Branch-free uniform inner loop, 3 independent accumulators for MLP.
// ---------------------------------------------------------------------------
__global__ void __launch_bounds__(256) k_stage2(const float* __restrict__ Lw,
                                                const float* __restrict__ Ew,
                                                const float* __restrict__ Nw,
                                                const int*   __restrict__ nbr,
                                                const float* __restrict__ bias,
                                                float* __restrict__ out)
{
    __shared__ int   s_j [32][KK];
    __shared__ float s_wL[32][KK], s_wE[32][KK], s_wN[32][KK];
    __shared__ int   s_cnt[32];
    __shared__ float tile[64][33];          // [o][vl], +1 pad
    __shared__ float ss[4][64], sq[4][64];

    const int b     = blockIdx.y;
    const int vbase = blockIdx.x * 32;
    const int tx    = threadIdx.x;          // o
    const int ty    = threadIdx.y;          // v sub-lane
    const int tid   = ty * 64 + tx;

    // Compact surviving neighbors (j < NVP) per vertex lane
    if (tid < 32) {
        int v = vbase + tid;
        int c = 0;
        if (v < NVV) {
            int gbase = v * KK;
#pragma unroll
            for (int k = 0; k < KK; k++) {
                int j = nbr[gbase + k];
                if (j < NVP) {
                    s_j [tid][c] = j;
                    s_wL[tid][c] = Lw[gbase + k];
                    s_wE[tid][c] = Ew[gbase + k];
                    s_wN[tid][c] = Nw[gbase + k];
                    c++;
                }
            }
        }
        s_cnt[tid] = c;
    }
    __syncthreads();

    const float* Yb = d_Y + (size_t)b * NVP * 256;
    const float  bo = bias[tx];
    float S = 0.f, Q = 0.f;

#pragma unroll
    for (int iter = 0; iter < 8; iter++) {
        int vl = iter * 4 + ty;
        int v  = vbase + vl;
        float acc = 0.f;
        if (v < NVV) {
            float aL = 0.f, aE = 0.f, aN = 0.f;
            acc = bo;
            if (v < NVP) acc += Yb[v * 256 + tx];
            int cnt = s_cnt[vl];                  // warp-uniform
            for (int kk = 0; kk < cnt; kk++) {
                const float* p = Yb + s_j[vl][kk] * 256 + tx;
                aL = fmaf(s_wL[vl][kk], p[64],  aL);
                aE = fmaf(s_wE[vl][kk], p[128], aE);
                aN = fmaf(s_wN[vl][kk], p[192], aN);
            }
            acc += aL + aE + aN;
            S += acc;
            Q = fmaf(acc, acc, Q);
        }
        tile[tx][vl] = acc;
    }
    ss[ty][tx] = S;
    sq[ty][tx] = Q;
    __syncthreads();

    // Transposed write-out: each thread writes 8 consecutive v of one o-row
    {
        int r   = tid >> 2;
        int seg = tid & 3;
        size_t rowbase = (size_t)(b * 64 + r) * NVV;
#pragma unroll
        for (int u = 0; u < 8; u++) {
            int vl = seg * 8 + u;
            int v  = vbase + vl;
            if (v < NVV) out[rowbase + v] = tile[r][vl];
        }
    }

    // Deterministic per-(b,group,vblk) partials: group g = channels {2g, 2g+1}
    if (tid < 32) {
        float Sg = 0.f, Qg = 0.f;
#pragma unroll
        for (int oo = 0; oo < 2; oo++)
#pragma unroll
            for (int yy = 0; yy < 4; yy++) {
                Sg += ss[yy][tid * 2 + oo];
                Qg += sq[yy][tid * 2 + oo];
            }
        d_psum[(b * 32 + tid) * VBLKS + blockIdx.x] = Sg;
        d_psq [(b * 32 + tid) * VBLKS + blockIdx.x] = Qg;
    }
}

// ---------------------------------------------------------------------------
// Stage 2.5: reduce partials -> mean / rstd per (b, group). Fixed-order.
// ---------------------------------------------------------------------------
__global__ void __launch_bounds__(256) k_reduce()
{
    __shared__ float sS[256], sQ[256];
    const int bg  = blockIdx.x;
    const int tid = threadIdx.x;
    float S = 0.f, Q = 0.f;
    for (int i = tid; i < VBLKS; i += 256) {
        S += d_psum[bg * VBLKS + i];
        Q += d_psq [bg * VBLKS + i];
    }
    sS[tid] = S; sQ[tid] = Q;
    __syncthreads();
    for (int st = 128; st > 0; st >>= 1) {
        if (tid < st) { sS[tid] += sS[tid + st]; sQ[tid] += sQ[tid + st]; }
        __syncthreads();
    }
    if (tid == 0) {
        float mean = sS[0] * (1.f / (float)GN_N);
        float var  = sQ[0] * (1.f / (float)GN_N) - mean * mean;
        d_mean[bg] = mean;
        d_rstd[bg] = rsqrtf(var + 1e-5f);
    }
}

// ---------------------------------------------------------------------------
// Stage 3: in-place normalize + affine + ReLU. float2, 8 elems/thread.
// Rows are NVV floats: NVV even -> row base 8B-aligned, NVV/2 = 20481 float2.
// ---------------------------------------------------------------------------
#define S3_V2   20481                   // float2 per row
#define S3_PERT 8                       // float2 per thread
__global__ void __launch_bounds__(256) k_stage3(float* __restrict__ out,
                                                const float* __restrict__ gamma,
                                                const float* __restrict__ beta)
{
    const int row = blockIdx.y;                 // b*64 + o
    const int o   = row & 63;
    const int bg  = (row >> 6) * 32 + (o >> 1);
    const float a = d_rstd[bg] * gamma[o];
    const float c = beta[o] - d_mean[bg] * a;

    float2* rp = (float2*)(out + (size_t)row * NVV);
    int base = blockIdx.x * (256 * S3_PERT) + threadIdx.x;
#pragma unroll
    for (int u = 0; u < S3_PERT; u++) {
        int i2 = base + u * 256;
        if (i2 < S3_V2) {
            float2 t = rp[i2];
            t.x = fmaxf(fmaf(t.x, a, c), 0.f);
            t.y = fmaxf(fmaf(t.y, a, c), 0.f);
            rp[i2] = t;
        }
    }
}

// ---------------------------------------------------------------------------
extern "C" void kernel_launch(void* const* d_in, const int* in_sizes, int n_in,
                              void* d_out, int out_size)
{
    const float* x      = (const float*)d_in[0];
    const float* L_val  = (const float*)d_in[1];
    const float* EW_val = (const float*)d_in[2];
    const float* NS_val = (const float*)d_in[3];
    const float* coeffs = (const float*)d_in[4];
    const float* bias   = (const float*)d_in[5];
    const float* gamma  = (const float*)d_in[6];
    const float* beta   = (const float*)d_in[7];
    const int*   nbr    = (const int*)  d_in[8];
    float*       out    = (float*)d_out;

    static bool configured = false;
    if (!configured) {
        cudaFuncSetAttribute(k_stage1, cudaFuncAttributeMaxDynamicSharedMemorySize,
                             64 * (TM + TN) * (int)sizeof(float));
        configured = true;
    }

    // Stage 1: Y projection GEMM (packed f32x2)
    {
        dim3 grid((NVP + TM - 1) / TM, 256 / TN, BB);   // (81, 2, 8)
        k_stage1<<<grid, 256, 64 * (TM + TN) * sizeof(float)>>>(x, coeffs);
    }
    // Stage 2: gather-combine + pre-GN out + partials
    {
        dim3 grid(VBLKS, BB);
        dim3 block(64, 4);
        k_stage2<<<grid, block>>>(L_val, EW_val, NS_val, nbr, bias, out);
    }
    // Stage 2.5: group statistics
    k_reduce<<<256, 256>>>();
    // Stage 3: normalize + ReLU (in place)
    {
        dim3 grid((S3_V2 + 256 * S3_PERT - 1) / (256 * S3_PERT), BB * CC);  // (11, 512)
        k_stage3<<<grid, 256>>>(out, gamma, beta);
    }
}

// round 5
// speedup vs baseline: 1.6636x; 1.1550x over previous
#include <cuda_runtime.h>
#include <cuda_fp16.h>
#include <cstddef>

#define NVV   40962
#define NVP   10242
#define BB    8
#define CC    64
#define KK    7
#define VBLKS 1281              // ceil(40962/32)
#define GN_N  (2*NVV)           // elements per groupnorm group

#define TM 128                  // v per stage1 block
// o per stage1 block = 32 (x4 s = 128 "so")

// Scratch (device globals — no allocations allowed)
__device__ float  d_Y0[(size_t)BB * NVP * 64];        // up-proj  [b][v][o], 21 MB
__device__ __half d_Yd[(size_t)BB * NVP * 64 * 4];    // {y1,y2,y3,0} [b][v][o][4], 42 MB
__device__ float  d_Bt[64 * 256];                     // coeffs transposed [i][o*4+s]
__device__ float  d_psum[256 * VBLKS];
__device__ float  d_psq [256 * VBLKS];
__device__ float  d_mean[256];
__device__ float  d_rstd[256];

#define FMA2(d, a, b, c) \
    asm("fma.rn.f32x2 %0, %1, %2, %3;" : "=l"(d) : "l"(a), "l"(b), "l"(c))

// ---------------------------------------------------------------------------
// Prep: transpose coeffs -> d_Bt[i][o*4+s]  (coalesced loads for stage1)
// ---------------------------------------------------------------------------
__global__ void k_prep(const float* __restrict__ coeffs)
{
    int t = blockIdx.x * 256 + threadIdx.x;      // 16384 total
    int i = t >> 8;
    int r = t & 255;
    int o = r >> 2;
    int s = r & 3;
    d_Bt[i * 256 + r] = coeffs[(o * 64 + i) * 4 + s];
}

// ---------------------------------------------------------------------------
// Stage 1: y_s[b,v,o] = sum_i coeffs[o,i,s] * x[b,i,v]
// Packed f32x2 FMA, per-block tile: 128 v x 32 o x 4 s.
// Thread tile: 8 v x 2 o x 4 s. Emits fp32 y0 + fp16 half4 {y1,y2,y3,0}.
// ---------------------------------------------------------------------------
__global__ void __launch_bounds__(256) k_stage1(const float* __restrict__ x)
{
    extern __shared__ float sm[];
    float* As = sm;              // [i][vl] : 64*128
    float* Bs = sm + 64 * TM;    // [i][ol*4+s] : 64*128

    const int b     = blockIdx.z;
    const int vbase = blockIdx.x * TM;
    const int obase = blockIdx.y * 32;
    const int tid   = threadIdx.x;

    // Bs[i][r] = d_Bt[i*256 + obase*4 + r]   (coalesced)
    for (int t = tid; t < 64 * 128; t += 256) {
        int i = t >> 7;
        int r = t & 127;
        Bs[t] = d_Bt[i * 256 + obase * 4 + r];
    }
    // As[i][vl], zero-padded past NVP
    for (int t = tid; t < 64 * TM; t += 256) {
        int i  = t >> 7;
        int vl = t & 127;
        int v  = vbase + vl;
        As[t]  = (v < NVP) ? x[(b * 64 + i) * NVP + v] : 0.f;
    }
    __syncthreads();

    const int ol0   = (tid & 15) * 2;    // 2 o per thread (16 lanes -> 32 o)
    const int v_sub = (tid >> 4) * 8;    // 8 v per thread (16 groups -> 128 v)

    unsigned long long acc[8][4];        // [olx*4+s][v-pair]
#pragma unroll
    for (int a = 0; a < 8; a++)
#pragma unroll
        for (int c = 0; c < 4; c++) acc[a][c] = 0ULL;

#pragma unroll 4
    for (int i = 0; i < 64; i++) {
        const ulonglong2* Ap = (const ulonglong2*)(As + i * TM + v_sub);
        ulonglong2 a01 = Ap[0];
        ulonglong2 a23 = Ap[1];
        unsigned long long av[4] = {a01.x, a01.y, a23.x, a23.y};
        float4 b0 = *(const float4*)(Bs + i * 128 + ol0 * 4);
        float4 b1 = *(const float4*)(Bs + i * 128 + ol0 * 4 + 4);
        float bv[8] = {b0.x, b0.y, b0.z, b0.w, b1.x, b1.y, b1.z, b1.w};
#pragma unroll
        for (int a = 0; a < 8; a++) {
            unsigned bu = __float_as_uint(bv[a]);
            unsigned long long bb;
            asm("mov.b64 %0, {%1, %1};" : "=l"(bb) : "r"(bu));
#pragma unroll
            for (int c = 0; c < 4; c++)
                FMA2(acc[a][c], av[c], bb, acc[a][c]);
        }
    }

    // Epilogue: per vertex write y0 (float2 over 2 o) + 2x half4
#pragma unroll
    for (int c = 0; c < 4; c++) {
#pragma unroll
        for (int par = 0; par < 2; par++) {
            int v = vbase + v_sub + c * 2 + par;
            if (v < NVP) {
                float w[8];
#pragma unroll
                for (int a = 0; a < 8; a++) {
                    unsigned long long u = acc[a][c];
                    w[a] = __uint_as_float(par ? (unsigned)(u >> 32)
                                               : (unsigned)(u & 0xffffffffULL));
                }
                size_t vb = (size_t)b * NVP + v;
                int o0 = obase + ol0;
                // y0 (s=0) for olx=0,1
                *(float2*)(d_Y0 + vb * 64 + o0) = make_float2(w[0], w[4]);
                // half4 {y1,y2,y3,0} for each o
                __half2 p0 = __floats2half2_rn(w[1], w[2]);
                __half2 p1 = __floats2half2_rn(w[3], 0.f);
                __half2 q0 = __floats2half2_rn(w[5], w[6]);
                __half2 q1 = __floats2half2_rn(w[7], 0.f);
                uint4 pk;
                pk.x = *(unsigned*)&p0; pk.y = *(unsigned*)&p1;
                pk.z = *(unsigned*)&q0; pk.w = *(unsigned*)&q1;
                *(uint4*)(d_Yd + (vb * 64 + o0) * 4) = pk;
            }
        }
    }
}

// ---------------------------------------------------------------------------
// Stage 2: gather-combine (one 8B load per neighbor hit) + pre-GN out +
// deterministic group partials.
// ---------------------------------------------------------------------------
__global__ void __launch_bounds__(256) k_stage2(const float* __restrict__ Lw,
                                                const float* __restrict__ Ew,
                                                const float* __restrict__ Nw,
                                                const int*   __restrict__ nbr,
                                                const float* __restrict__ bias,
                                                float* __restrict__ out)
{
    __shared__ int   s_rj[32 * KK];
    __shared__ float s_rL[32 * KK], s_rE[32 * KK], s_rN[32 * KK];
    __shared__ int   s_j [32][KK];
    __shared__ float s_wL[32][KK], s_wE[32][KK], s_wN[32][KK];
    __shared__ int   s_cnt[32];
    __shared__ float tile[64][33];
    __shared__ float ss[4][64], sq[4][64];

    const int b     = blockIdx.y;
    const int vbase = blockIdx.x * 32;
    const int tx    = threadIdx.x;          // o
    const int ty    = threadIdx.y;          // v sub-lane
    const int tid   = ty * 64 + tx;

    // Parallel raw load of neighbor data
    if (tid < 32 * KK) {
        int gidx = vbase * KK + tid;
        if (gidx < NVV * KK) {
            s_rj[tid] = nbr[gidx];
            s_rL[tid] = Lw[gidx]; s_rE[tid] = Ew[gidx]; s_rN[tid] = Nw[gidx];
        } else {
            s_rj[tid] = NVP;
        }
    }
    __syncthreads();
    // Compact surviving neighbors (j < NVP)
    if (tid < 32) {
        int c = 0;
#pragma unroll
        for (int k = 0; k < KK; k++) {
            int j = s_rj[tid * KK + k];
            if (j < NVP) {
                s_j [tid][c] = j;
                s_wL[tid][c] = s_rL[tid * KK + k];
                s_wE[tid][c] = s_rE[tid * KK + k];
                s_wN[tid][c] = s_rN[tid * KK + k];
                c++;
            }
        }
        s_cnt[tid] = c;
    }
    __syncthreads();

    const float* Y0b = d_Y0 + (size_t)b * NVP * 64;
    const __half* Ydb = d_Yd + (size_t)b * NVP * 256;
    const float  bo = bias[tx];
    float S = 0.f, Q = 0.f;

#pragma unroll
    for (int iter = 0; iter < 8; iter++) {
        int vl = iter * 4 + ty;
        int v  = vbase + vl;
        float acc = 0.f;
        if (v < NVV) {
            float aL = 0.f, aE = 0.f, aN = 0.f;
            acc = bo;
            if (v < NVP) acc += Y0b[v * 64 + tx];
            int cnt = s_cnt[vl];                  // warp-uniform
            for (int kk = 0; kk < cnt; kk++) {
                uint2 q = *(const uint2*)(Ydb + ((size_t)s_j[vl][kk] * 64 + tx) * 4);
                float2 f01 = __half22float2(*(__half2*)&q.x);
                float2 f23 = __half22float2(*(__half2*)&q.y);
                aL = fmaf(s_wL[vl][kk], f01.x, aL);
                aE = fmaf(s_wE[vl][kk], f01.y, aE);
                aN = fmaf(s_wN[vl][kk], f23.x, aN);
            }
            acc += aL + aE + aN;
            S += acc;
            Q = fmaf(acc, acc, Q);
        }
        tile[tx][vl] = acc;
    }
    ss[ty][tx] = S;
    sq[ty][tx] = Q;
    __syncthreads();

    // Transposed write-out: each thread writes 8 consecutive v of one o-row
    {
        int r   = tid >> 2;
        int seg = tid & 3;
        size_t rowbase = (size_t)(b * 64 + r) * NVV;
#pragma unroll
        for (int u = 0; u < 8; u++) {
            int vl = seg * 8 + u;
            int v  = vbase + vl;
            if (v < NVV) out[rowbase + v] = tile[r][vl];
        }
    }

    // Deterministic per-(b,group,vblk) partials
    if (tid < 32) {
        float Sg = 0.f, Qg = 0.f;
#pragma unroll
        for (int oo = 0; oo < 2; oo++)
#pragma unroll
            for (int yy = 0; yy < 4; yy++) {
                Sg += ss[yy][tid * 2 + oo];
                Qg += sq[yy][tid * 2 + oo];
            }
        d_psum[(b * 32 + tid) * VBLKS + blockIdx.x] = Sg;
        d_psq [(b * 32 + tid) * VBLKS + blockIdx.x] = Qg;
    }
}

// ---------------------------------------------------------------------------
// Stage 2.5: reduce partials -> mean / rstd per (b, group). Fixed-order.
// ---------------------------------------------------------------------------
__global__ void __launch_bounds__(256) k_reduce()
{
    __shared__ float sS[256], sQ[256];
    const int bg  = blockIdx.x;
    const int tid = threadIdx.x;
    float S = 0.f, Q = 0.f;
    for (int i = tid; i < VBLKS; i += 256) {
        S += d_psum[bg * VBLKS + i];
        Q += d_psq [bg * VBLKS + i];
    }
    sS[tid] = S; sQ[tid] = Q;
    __syncthreads();
    for (int st = 128; st > 0; st >>= 1) {
        if (tid < st) { sS[tid] += sS[tid + st]; sQ[tid] += sQ[tid + st]; }
        __syncthreads();
    }
    if (tid == 0) {
        float mean = sS[0] * (1.f / (float)GN_N);
        float var  = sQ[0] * (1.f / (float)GN_N) - mean * mean;
        d_mean[bg] = mean;
        d_rstd[bg] = rsqrtf(var + 1e-5f);
    }
}

// ---------------------------------------------------------------------------
// Stage 3: normalize + affine + ReLU, float4 over row-pairs.
// 2*NVV = 81924 floats = 20481 float4 per pair-row. Boundary f4 = #10240.
// ---------------------------------------------------------------------------
#define S3_F4   20481
#define S3_PERT 8
__global__ void __launch_bounds__(256) k_stage3(float* __restrict__ out,
                                                const float* __restrict__ gamma,
                                                const float* __restrict__ beta)
{
    const int pr   = blockIdx.y;                // pair-row: rows 2pr, 2pr+1
    const int row0 = pr * 2;
    const int o0   = row0 & 63;
    const int o1   = o0 + 1;
    const int bgb  = (row0 >> 6) * 32;
    const float a0 = d_rstd[bgb + (o0 >> 1)] * gamma[o0];
    const float c0 = beta[o0] - d_mean[bgb + (o0 >> 1)] * a0;
    const float a1 = d_rstd[bgb + (o1 >> 1)] * gamma[o1];
    const float c1 = beta[o1] - d_mean[bgb + (o1 >> 1)] * a1;

    float4* base = (float4*)(out + (size_t)pr * 2 * NVV);
    int i0 = blockIdx.x * (256 * S3_PERT) + threadIdx.x;
#pragma unroll
    for (int u = 0; u < S3_PERT; u++) {
        int i4 = i0 + u * 256;
        if (i4 < S3_F4) {
            float4 t = base[i4];
            float ax, cx, az, cz;
            if (i4 < 10240)      { ax = a0; cx = c0; az = a0; cz = c0; }
            else if (i4 > 10240) { ax = a1; cx = c1; az = a1; cz = c1; }
            else                 { ax = a0; cx = c0; az = a1; cz = c1; }
            t.x = fmaxf(fmaf(t.x, ax, cx), 0.f);
            t.y = fmaxf(fmaf(t.y, ax, cx), 0.f);
            t.z = fmaxf(fmaf(t.z, az, cz), 0.f);
            t.w = fmaxf(fmaf(t.w, az, cz), 0.f);
            base[i4] = t;
        }
    }
}

// ---------------------------------------------------------------------------
extern "C" void kernel_launch(void* const* d_in, const int* in_sizes, int n_in,
                              void* d_out, int out_size)
{
    const float* x      = (const float*)d_in[0];
    const float* L_val  = (const float*)d_in[1];
    const float* EW_val = (const float*)d_in[2];
    const float* NS_val = (const float*)d_in[3];
    const float* coeffs = (const float*)d_in[4];
    const float* bias   = (const float*)d_in[5];
    const float* gamma  = (const float*)d_in[6];
    const float* beta   = (const float*)d_in[7];
    const int*   nbr    = (const int*)  d_in[8];
    float*       out    = (float*)d_out;

    static bool configured = false;
    if (!configured) {
        cudaFuncSetAttribute(k_stage1, cudaFuncAttributeMaxDynamicSharedMemorySize,
                             64 * (TM + 128) * (int)sizeof(float));
        configured = true;
    }

    // Prep: coeffs transpose
    k_prep<<<64, 256>>>(coeffs);
    // Stage 1: projection GEMM -> d_Y0 (fp32) + d_Yd (fp16 half4)
    {
        dim3 grid((NVP + TM - 1) / TM, 2, BB);          // (81, 2, 8)
        k_stage1<<<grid, 256, 64 * (TM + 128) * sizeof(float)>>>(x);
    }
    // Stage 2: gather-combine + pre-GN out + partials
    {
        dim3 grid(VBLKS, BB);
        dim3 block(64, 4);
        k_stage2<<<grid, block>>>(L_val, EW_val, NS_val, nbr, bias, out);
    }
    // Stage 2.5: group statistics
    k_reduce<<<256, 256>>>();
    // Stage 3: normalize + ReLU (in place), float4 over row-pairs
    {
        dim3 grid((S3_F4 + 256 * S3_PERT - 1) / (256 * S3_PERT), BB * CC / 2);
        k_stage3<<<grid, 256>>>(out, gamma, beta);
    }
}